// round 1
// baseline (speedup 1.0000x reference)
#include <cuda_runtime.h>

#define NN 100000
#define DD 128
#define RB 64            // rows per MLP block
#define EPW 64           // edges per warp in spmm

#define SELU_SCALE 1.0507009873554805f
#define SELU_ALPHA 1.6732632423543772f

// Scratch: h_i = spmm(x_in^(i+1)) + x_in^(i+1)   (residual folded into init)
__device__ float g_h0[NN * DD];
__device__ float g_h1[NN * DD];

__device__ __forceinline__ float selu_f(float x) {
    return x > 0.f ? SELU_SCALE * x
                   : (SELU_SCALE * SELU_ALPHA) * (__expf(x) - 1.f);
}

// ---------------------------------------------------------------------------
// Kernel 1: h0 = x_in ; h1 = x_in * x_in   (residual pre-init)
// ---------------------------------------------------------------------------
__global__ void init_h_kernel(const float4* __restrict__ x4, int n4) {
    int i = blockIdx.x * blockDim.x + threadIdx.x;
    if (i >= n4) return;
    float4 v = __ldg(&x4[i]);
    ((float4*)g_h0)[i] = v;
    ((float4*)g_h1)[i] = make_float4(v.x * v.x, v.y * v.y, v.z * v.z, v.w * v.w);
}

// ---------------------------------------------------------------------------
// Kernel 2: fused dual-branch SpMM.
// One warp owns EPW consecutive edges; lane l owns dims [4l, 4l+4).
// Rows are sorted, so accumulate in registers until the row changes, then
// flush with atomicAdd (segment boundaries + chunk boundaries only).
// Both branches share ONE gather of x_in[col]:  a0 += v*g ; a1 += v*g*g.
// ---------------------------------------------------------------------------
__device__ __forceinline__ void flush_row(int r, int lane,
                                          const float4& a0, const float4& a1) {
    float* p0 = g_h0 + (size_t)r * DD + lane * 4;
    float* p1 = g_h1 + (size_t)r * DD + lane * 4;
    atomicAdd(p0 + 0, a0.x); atomicAdd(p0 + 1, a0.y);
    atomicAdd(p0 + 2, a0.z); atomicAdd(p0 + 3, a0.w);
    atomicAdd(p1 + 0, a1.x); atomicAdd(p1 + 1, a1.y);
    atomicAdd(p1 + 2, a1.z); atomicAdd(p1 + 3, a1.w);
}

__global__ void spmm_kernel(const float4* __restrict__ x4,
                            const int*    __restrict__ erow,
                            const int*    __restrict__ ecol,
                            const float*  __restrict__ evalv,
                            int E) {
    int gw   = (blockIdx.x * blockDim.x + threadIdx.x) >> 5;
    int lane = threadIdx.x & 31;
    int e0 = gw * EPW;
    if (e0 >= E) return;
    int e1 = min(e0 + EPW, E);

    float4 a0 = make_float4(0.f, 0.f, 0.f, 0.f);
    float4 a1 = make_float4(0.f, 0.f, 0.f, 0.f);
    int cur = __ldg(erow + e0);

    for (int e = e0; e < e1; ++e) {
        int r = __ldg(erow + e);
        if (r != cur) {
            flush_row(cur, lane, a0, a1);
            a0 = make_float4(0.f, 0.f, 0.f, 0.f);
            a1 = make_float4(0.f, 0.f, 0.f, 0.f);
            cur = r;
        }
        int   c = __ldg(ecol + e);
        float v = __ldg(evalv + e);
        float4 g = __ldg(&x4[(size_t)c * 32 + lane]);
        a0.x = fmaf(v, g.x, a0.x);
        a0.y = fmaf(v, g.y, a0.y);
        a0.z = fmaf(v, g.z, a0.z);
        a0.w = fmaf(v, g.w, a0.w);
        float vx = v * g.x, vy = v * g.y, vz = v * g.z, vw = v * g.w;
        a1.x = fmaf(vx, g.x, a1.x);
        a1.y = fmaf(vy, g.y, a1.y);
        a1.z = fmaf(vz, g.z, a1.z);
        a1.w = fmaf(vw, g.w, a1.w);
    }
    flush_row(cur, lane, a0, a1);
}

// ---------------------------------------------------------------------------
// Kernel 3: fused 2-layer MLP per branch.
//   t   = selu(h @ W1[br] + b1[br])      (t kept in shared, never hits global)
//   out = selu(t @ W2[br] + b2[br])      -> d_out[:, br*128 : br*128+128]
// Block: 256 threads, 64-row tile. Warp w owns rows [8w, 8w+8); lane l owns
// cols [4l, 4l+4). Shared: W (64KB) + A tile (32KB) + T tile (32KB) = 128KB.
// ---------------------------------------------------------------------------
__global__ void mlp_kernel(const float* __restrict__ W1,
                           const float* __restrict__ b1,
                           const float* __restrict__ W2,
                           const float* __restrict__ b2,
                           float* __restrict__ out, int n) {
    extern __shared__ float sm[];
    float* sW = sm;                   // 128*128
    float* sA = sm + DD * DD;         // RB*128
    float* sT = sA + RB * DD;         // RB*128

    int br = blockIdx.y;
    const float* h = br ? g_h1 : g_h0;
    int r0   = blockIdx.x * RB;
    int rows = min(RB, n - r0);
    int tid  = threadIdx.x;
    int warp = tid >> 5, lane = tid & 31;

    // load W1[br] into shared
    const float4* w1g = (const float4*)(W1 + (size_t)br * DD * DD);
    float4* sW4 = (float4*)sW;
    #pragma unroll
    for (int i = tid; i < DD * DD / 4; i += 256) sW4[i] = __ldg(&w1g[i]);

    // load A tile (zero-fill tail rows)
    const float4* hg = (const float4*)(h + (size_t)r0 * DD);
    float4* sA4 = (float4*)sA;
    for (int i = tid; i < RB * DD / 4; i += 256)
        sA4[i] = (i < rows * (DD / 4)) ? __ldg(&hg[i])
                                       : make_float4(0.f, 0.f, 0.f, 0.f);
    __syncthreads();

    // ---- stage 1: T = selu(A @ W1 + b1) ----
    float4 acc[8];
    {
        float4 bias = __ldg(&((const float4*)(b1 + (size_t)br * DD))[lane]);
        #pragma unroll
        for (int i = 0; i < 8; ++i) acc[i] = bias;
    }
    #pragma unroll 4
    for (int k = 0; k < DD; ++k) {
        float4 w = *(const float4*)(sW + k * DD + lane * 4);
        const float* ap = sA + warp * 8 * DD + k;
        #pragma unroll
        for (int i = 0; i < 8; ++i) {
            float a = ap[i * DD];
            acc[i].x = fmaf(a, w.x, acc[i].x);
            acc[i].y = fmaf(a, w.y, acc[i].y);
            acc[i].z = fmaf(a, w.z, acc[i].z);
            acc[i].w = fmaf(a, w.w, acc[i].w);
        }
    }
    #pragma unroll
    for (int i = 0; i < 8; ++i) {
        float4 t;
        t.x = selu_f(acc[i].x); t.y = selu_f(acc[i].y);
        t.z = selu_f(acc[i].z); t.w = selu_f(acc[i].w);
        *(float4*)(sT + (warp * 8 + i) * DD + lane * 4) = t;
    }
    __syncthreads();   // all stage-1 reads of sW done; sT complete

    // overwrite sW with W2[br]
    const float4* w2g = (const float4*)(W2 + (size_t)br * DD * DD);
    #pragma unroll
    for (int i = tid; i < DD * DD / 4; i += 256) sW4[i] = __ldg(&w2g[i]);
    __syncthreads();

    // ---- stage 2: out = selu(T @ W2 + b2) ----
    {
        float4 bias = __ldg(&((const float4*)(b2 + (size_t)br * DD))[lane]);
        #pragma unroll
        for (int i = 0; i < 8; ++i) acc[i] = bias;
    }
    #pragma unroll 4
    for (int k = 0; k < DD; ++k) {
        float4 w = *(const float4*)(sW + k * DD + lane * 4);
        const float* ap = sT + warp * 8 * DD + k;
        #pragma unroll
        for (int i = 0; i < 8; ++i) {
            float a = ap[i * DD];
            acc[i].x = fmaf(a, w.x, acc[i].x);
            acc[i].y = fmaf(a, w.y, acc[i].y);
            acc[i].z = fmaf(a, w.z, acc[i].z);
            acc[i].w = fmaf(a, w.w, acc[i].w);
        }
    }
    #pragma unroll
    for (int i = 0; i < 8; ++i) {
        int r = warp * 8 + i;
        if (r < rows) {
            float4 t;
            t.x = selu_f(acc[i].x); t.y = selu_f(acc[i].y);
            t.z = selu_f(acc[i].z); t.w = selu_f(acc[i].w);
            *(float4*)(out + (size_t)(r0 + r) * (2 * DD) + br * DD + lane * 4) = t;
        }
    }
}

// ---------------------------------------------------------------------------
extern "C" void kernel_launch(void* const* d_in, const int* in_sizes, int n_in,
                              void* d_out, int out_size) {
    const float* x_in = (const float*)d_in[0];
    const int*   erow = (const int*)d_in[1];
    const int*   ecol = (const int*)d_in[2];
    const float* evalv = (const float*)d_in[3];
    const float* W1 = (const float*)d_in[4];
    const float* b1 = (const float*)d_in[5];
    const float* W2 = (const float*)d_in[6];
    const float* b2 = (const float*)d_in[7];
    float* out = (float*)d_out;

    int n = in_sizes[0] / DD;      // 100000
    int E = in_sizes[1];           // 1600000

    int n4 = n * DD / 4;
    init_h_kernel<<<(n4 + 255) / 256, 256>>>((const float4*)x_in, n4);

    int warps = (E + EPW - 1) / EPW;
    int sblocks = (warps * 32 + 255) / 256;
    spmm_kernel<<<sblocks, 256>>>((const float4*)x_in, erow, ecol, evalv, E);

    int smem = (DD * DD + 2 * RB * DD) * (int)sizeof(float);   // 128 KB
    cudaFuncSetAttribute(mlp_kernel, cudaFuncAttributeMaxDynamicSharedMemorySize, smem);
    dim3 grid((n + RB - 1) / RB, 2);
    mlp_kernel<<<grid, 256, smem>>>(W1, b1, W2, b2, out, n);
}

// round 3
// speedup vs baseline: 1.1637x; 1.1637x over previous
#include <cuda_runtime.h>

#define NN 100000
#define DD 128
#define RB 128            // rows per MLP block
#define MLP_THREADS 512
#define EPW 64            // edges per warp in spmm

#define SELU_SCALE 1.0507009873554805f
#define SELU_ALPHA 1.6732632423543772f

typedef unsigned long long u64;

// Scratch: h_i = spmm(x_in^(i+1)) + x_in^(i+1)   (residual folded into init)
__device__ float g_h0[NN * DD];
__device__ float g_h1[NN * DD];

__device__ __forceinline__ float selu_f(float x) {
    return x > 0.f ? SELU_SCALE * x
                   : (SELU_SCALE * SELU_ALPHA) * (__expf(x) - 1.f);
}

// ---- f32x2 packed helpers (sm_100a) ----
__device__ __forceinline__ u64 dup2(float x) {
    u64 r; asm("mov.b64 %0, {%1, %1};" : "=l"(r) : "f"(x)); return r;
}
__device__ __forceinline__ u64 pk2(float x, float y) {
    u64 r; asm("mov.b64 %0, {%1, %2};" : "=l"(r) : "f"(x), "f"(y)); return r;
}
__device__ __forceinline__ float2 upk(u64 v) {
    float2 r; asm("mov.b64 {%0, %1}, %2;" : "=f"(r.x), "=f"(r.y) : "l"(v)); return r;
}
__device__ __forceinline__ void fma2(u64& d, u64 a, u64 b) {
#if defined(__CUDA_ARCH__) && (__CUDA_ARCH__ >= 1000)
    asm("fma.rn.f32x2 %0, %1, %2, %0;" : "+l"(d) : "l"(a), "l"(b));
#else
    float2 dd = upk(d), aa = upk(a), bb = upk(b);
    dd.x = fmaf(aa.x, bb.x, dd.x);
    dd.y = fmaf(aa.y, bb.y, dd.y);
    d = pk2(dd.x, dd.y);
#endif
}
// even swizzle term: keeps row-pairs aligned & ordered, spreads banks
#define SWF(k) ((((k) >> 3) << 1) & 31)

// ---------------------------------------------------------------------------
// Kernel 1: h0 = x_in ; h1 = x_in * x_in   (residual pre-init)
// ---------------------------------------------------------------------------
__global__ void init_h_kernel(const float4* __restrict__ x4, int n4) {
    int i = blockIdx.x * blockDim.x + threadIdx.x;
    if (i >= n4) return;
    float4 v = __ldg(&x4[i]);
    ((float4*)g_h0)[i] = v;
    ((float4*)g_h1)[i] = make_float4(v.x * v.x, v.y * v.y, v.z * v.z, v.w * v.w);
}

// ---------------------------------------------------------------------------
// Kernel 2: fused dual-branch SpMM, 4-edge batched gathers (MLP=4).
// ---------------------------------------------------------------------------
__device__ __forceinline__ void flush_row(int r, int lane,
                                          const float4& a0, const float4& a1) {
    float* p0 = g_h0 + (size_t)r * DD + lane * 4;
    float* p1 = g_h1 + (size_t)r * DD + lane * 4;
    atomicAdd(p0 + 0, a0.x); atomicAdd(p0 + 1, a0.y);
    atomicAdd(p0 + 2, a0.z); atomicAdd(p0 + 3, a0.w);
    atomicAdd(p1 + 0, a1.x); atomicAdd(p1 + 1, a1.y);
    atomicAdd(p1 + 2, a1.z); atomicAdd(p1 + 3, a1.w);
}

__global__ void spmm_kernel(const float4* __restrict__ x4,
                            const int*    __restrict__ erow,
                            const int*    __restrict__ ecol,
                            const float*  __restrict__ evalv,
                            int E) {
    int gw   = (blockIdx.x * blockDim.x + threadIdx.x) >> 5;
    int lane = threadIdx.x & 31;
    int e0 = gw * EPW;
    if (e0 >= E) return;
    int e1 = min(e0 + EPW, E);

    float4 a0 = make_float4(0.f, 0.f, 0.f, 0.f);
    float4 a1 = make_float4(0.f, 0.f, 0.f, 0.f);
    int cur = __ldg(erow + e0);

#define ACC1(RR, VV, GG)                                                       \
    do {                                                                       \
        if ((RR) != cur) {                                                     \
            flush_row(cur, lane, a0, a1);                                      \
            a0 = make_float4(0.f, 0.f, 0.f, 0.f);                              \
            a1 = make_float4(0.f, 0.f, 0.f, 0.f);                              \
            cur = (RR);                                                        \
        }                                                                      \
        a0.x = fmaf((VV), (GG).x, a0.x);                                       \
        a0.y = fmaf((VV), (GG).y, a0.y);                                       \
        a0.z = fmaf((VV), (GG).z, a0.z);                                       \
        a0.w = fmaf((VV), (GG).w, a0.w);                                       \
        float vx = (VV) * (GG).x, vy = (VV) * (GG).y;                          \
        float vz = (VV) * (GG).z, vw = (VV) * (GG).w;                          \
        a1.x = fmaf(vx, (GG).x, a1.x);                                         \
        a1.y = fmaf(vy, (GG).y, a1.y);                                         \
        a1.z = fmaf(vz, (GG).z, a1.z);                                         \
        a1.w = fmaf(vw, (GG).w, a1.w);                                         \
    } while (0)

    int e = e0;
    for (; e + 4 <= e1; e += 4) {
        int4   r4 = *(const int4*)(erow + e);     // e0 multiple of 64 -> aligned
        int4   c4 = *(const int4*)(ecol + e);
        float4 v4 = *(const float4*)(evalv + e);
        float4 g0 = __ldg(&x4[(size_t)c4.x * 32 + lane]);
        float4 g1 = __ldg(&x4[(size_t)c4.y * 32 + lane]);
        float4 g2 = __ldg(&x4[(size_t)c4.z * 32 + lane]);
        float4 g3 = __ldg(&x4[(size_t)c4.w * 32 + lane]);
        ACC1(r4.x, v4.x, g0);
        ACC1(r4.y, v4.y, g1);
        ACC1(r4.z, v4.z, g2);
        ACC1(r4.w, v4.w, g3);
    }
    for (; e < e1; ++e) {
        int   r = __ldg(erow + e);
        int   c = __ldg(ecol + e);
        float v = __ldg(evalv + e);
        float4 g = __ldg(&x4[(size_t)c * 32 + lane]);
        ACC1(r, v, g);
    }
    flush_row(cur, lane, a0, a1);
#undef ACC1
}

// ---------------------------------------------------------------------------
// Kernel 3: fused 2-layer MLP per branch, f32x2 packed FMA (row pairs).
// 512 threads, 128-row tile. Warp w owns rows [8w,8w+8) = 4 row-pairs;
// lane l owns cols [4l,4l+4). A and T tiles stored TRANSPOSED [k][row]
// with even XOR swizzle: stores 2-way conflicted, compute reads broadcast.
// Shared: W 64KB + AT 64KB + TT 64KB = 192KB -> 1 block/SM.
// ---------------------------------------------------------------------------
__global__ void __launch_bounds__(MLP_THREADS, 1)
mlp_kernel(const float* __restrict__ W1, const float* __restrict__ b1,
           const float* __restrict__ W2, const float* __restrict__ b2,
           float* __restrict__ out, int n) {
    extern __shared__ float sm[];
    float* sW  = sm;                 // 128*128 row-major [k][n]
    float* sAT = sm + DD * DD;       // [k][row^swf(k)]
    float* sTT = sAT + DD * RB;      // [c][row^swf(c)]

    int br = blockIdx.y;
    const float* h = br ? g_h1 : g_h0;
    int r0   = blockIdx.x * RB;
    int rows = min(RB, n - r0);
    int tid  = threadIdx.x;
    int warp = tid >> 5, lane = tid & 31;
    int rw = warp * 8;
    int c0 = lane * 4;

    // load W1[br] into shared (coalesced, conflict-free)
    const float4* w1g = (const float4*)(W1 + (size_t)br * DD * DD);
    float4* sW4 = (float4*)sW;
    for (int i = tid; i < DD * DD / 4; i += MLP_THREADS) sW4[i] = __ldg(&w1g[i]);

    // load A tile transposed+swizzled (one warp = one row, 2-way store conflicts)
    const float* hg = h + (size_t)r0 * DD;
    for (int i = tid; i < RB * (DD / 4); i += MLP_THREADS) {
        int row = i >> 5;            // 0..127
        int kq  = i & 31;
        float4 v = (row < rows) ? __ldg((const float4*)(hg + (size_t)row * DD + kq * 4))
                                : make_float4(0.f, 0.f, 0.f, 0.f);
        int k = kq * 4, f = SWF(k);  // same f for k..k+3
        sAT[(k + 0) * RB + (row ^ f)] = v.x;
        sAT[(k + 1) * RB + (row ^ f)] = v.y;
        sAT[(k + 2) * RB + (row ^ f)] = v.z;
        sAT[(k + 3) * RB + (row ^ f)] = v.w;
    }
    __syncthreads();

    u64 acc[4][4];   // [row-pair][col], f32x2 = {row even, row odd}

    // ---- stage 1: T = selu(A @ W1 + b1) ----
    {
        float4 bv = *(const float4*)(b1 + (size_t)br * DD + c0);
        u64 d0 = dup2(bv.x), d1 = dup2(bv.y), d2 = dup2(bv.z), d3 = dup2(bv.w);
        #pragma unroll
        for (int p = 0; p < 4; ++p) {
            acc[p][0] = d0; acc[p][1] = d1; acc[p][2] = d2; acc[p][3] = d3;
        }
    }
    #pragma unroll 2
    for (int k = 0; k < DD; ++k) {
        float4 wv = *(const float4*)(sW + k * DD + c0);
        u64 w0 = dup2(wv.x), w1d = dup2(wv.y), w2d = dup2(wv.z), w3d = dup2(wv.w);
        const float* ap = sAT + k * RB;
        int f = SWF(k);
        #pragma unroll
        for (int p = 0; p < 4; ++p) {
            u64 a = *(const u64*)(ap + ((rw + 2 * p) ^ f));   // broadcast
            fma2(acc[p][0], a, w0);
            fma2(acc[p][1], a, w1d);
            fma2(acc[p][2], a, w2d);
            fma2(acc[p][3], a, w3d);
        }
    }
    #pragma unroll
    for (int p = 0; p < 4; ++p) {
        #pragma unroll
        for (int j = 0; j < 4; ++j) {
            float2 t = upk(acc[p][j]);
            int c = c0 + j, f = SWF(c);
            *(u64*)(sTT + c * RB + ((rw + 2 * p) ^ f)) = pk2(selu_f(t.x), selu_f(t.y));
        }
    }
    __syncthreads();   // stage-1 sW reads + sTT writes complete

    // overwrite sW with W2[br]
    const float4* w2g = (const float4*)(W2 + (size_t)br * DD * DD);
    for (int i = tid; i < DD * DD / 4; i += MLP_THREADS) sW4[i] = __ldg(&w2g[i]);
    __syncthreads();

    // ---- stage 2: out = selu(T @ W2 + b2) ----
    {
        float4 bv = *(const float4*)(b2 + (size_t)br * DD + c0);
        u64 d0 = dup2(bv.x), d1 = dup2(bv.y), d2 = dup2(bv.z), d3 = dup2(bv.w);
        #pragma unroll
        for (int p = 0; p < 4; ++p) {
            acc[p][0] = d0; acc[p][1] = d1; acc[p][2] = d2; acc[p][3] = d3;
        }
    }
    #pragma unroll 2
    for (int k = 0; k < DD; ++k) {
        float4 wv = *(const float4*)(sW + k * DD + c0);
        u64 w0 = dup2(wv.x), w1d = dup2(wv.y), w2d = dup2(wv.z), w3d = dup2(wv.w);
        const float* ap = sTT + k * RB;
        int f = SWF(k);
        #pragma unroll
        for (int p = 0; p < 4; ++p) {
            u64 a = *(const u64*)(ap + ((rw + 2 * p) ^ f));
            fma2(acc[p][0], a, w0);
            fma2(acc[p][1], a, w1d);
            fma2(acc[p][2], a, w2d);
            fma2(acc[p][3], a, w3d);
        }
    }
    #pragma unroll
    for (int p = 0; p < 4; ++p) {
        int ra = rw + 2 * p;
        float2 t0 = upk(acc[p][0]), t1 = upk(acc[p][1]);
        float2 t2 = upk(acc[p][2]), t3 = upk(acc[p][3]);
        if (ra < rows) {
            float4 o = make_float4(selu_f(t0.x), selu_f(t1.x), selu_f(t2.x), selu_f(t3.x));
            *(float4*)(out + (size_t)(r0 + ra) * (2 * DD) + br * DD + c0) = o;
        }
        if (ra + 1 < rows) {
            float4 o = make_float4(selu_f(t0.y), selu_f(t1.y), selu_f(t2.y), selu_f(t3.y));
            *(float4*)(out + (size_t)(r0 + ra + 1) * (2 * DD) + br * DD + c0) = o;
        }
    }
}

// ---------------------------------------------------------------------------
extern "C" void kernel_launch(void* const* d_in, const int* in_sizes, int n_in,
                              void* d_out, int out_size) {
    const float* x_in  = (const float*)d_in[0];
    const int*   erow  = (const int*)d_in[1];
    const int*   ecol  = (const int*)d_in[2];
    const float* evalv = (const float*)d_in[3];
    const float* W1 = (const float*)d_in[4];
    const float* b1 = (const float*)d_in[5];
    const float* W2 = (const float*)d_in[6];
    const float* b2 = (const float*)d_in[7];
    float* out = (float*)d_out;

    int n = in_sizes[0] / DD;      // 100000
    int E = in_sizes[1];           // 1600000

    int n4 = n * DD / 4;
    init_h_kernel<<<(n4 + 255) / 256, 256>>>((const float4*)x_in, n4);

    int warps = (E + EPW - 1) / EPW;
    int sblocks = (warps * 32 + 255) / 256;
    spmm_kernel<<<sblocks, 256>>>((const float4*)x_in, erow, ecol, evalv, E);

    int smem = (DD * DD + 2 * DD * RB) * (int)sizeof(float);   // 192 KB
    cudaFuncSetAttribute(mlp_kernel, cudaFuncAttributeMaxDynamicSharedMemorySize, smem);
    dim3 grid((n + RB - 1) / RB, 2);
    mlp_kernel<<<grid, MLP_THREADS, smem>>>(W1, b1, W2, b2, out, n);
}

// round 7
// speedup vs baseline: 1.2613x; 1.0839x over previous
#include <cuda_runtime.h>
#include <cuda_bf16.h>
#include <cstdint>

#define NN 100000
#define DD 128
#define EPW 64            // edges per warp in spmm

#define SELU_SCALE 1.0507009873554805f
#define SELU_ALPHA 1.6732632423543772f

// Scratch: h_i = spmm(x_in^(i+1)) + x_in^(i+1)   (residual folded into init)
__device__ float g_h0[NN * DD];
__device__ float g_h1[NN * DD];

__device__ __forceinline__ float selu_f(float x) {
    return x > 0.f ? SELU_SCALE * x
                   : (SELU_SCALE * SELU_ALPHA) * (__expf(x) - 1.f);
}

// ---------------------------------------------------------------------------
// Kernel 1: h0 = x_in ; h1 = x_in * x_in   (residual pre-init)
// ---------------------------------------------------------------------------
__global__ void init_h_kernel(const float4* __restrict__ x4, int n4) {
    int i = blockIdx.x * blockDim.x + threadIdx.x;
    if (i >= n4) return;
    float4 v = __ldg(&x4[i]);
    ((float4*)g_h0)[i] = v;
    ((float4*)g_h1)[i] = make_float4(v.x * v.x, v.y * v.y, v.z * v.z, v.w * v.w);
}

// ---------------------------------------------------------------------------
// Kernel 2: fused dual-branch SpMM, 4-edge batched gathers (unchanged)
// ---------------------------------------------------------------------------
__device__ __forceinline__ void flush_row(int r, int lane,
                                          const float4& a0, const float4& a1) {
    float* p0 = g_h0 + (size_t)r * DD + lane * 4;
    float* p1 = g_h1 + (size_t)r * DD + lane * 4;
    atomicAdd(p0 + 0, a0.x); atomicAdd(p0 + 1, a0.y);
    atomicAdd(p0 + 2, a0.z); atomicAdd(p0 + 3, a0.w);
    atomicAdd(p1 + 0, a1.x); atomicAdd(p1 + 1, a1.y);
    atomicAdd(p1 + 2, a1.z); atomicAdd(p1 + 3, a1.w);
}

__global__ void spmm_kernel(const float4* __restrict__ x4,
                            const int*    __restrict__ erow,
                            const int*    __restrict__ ecol,
                            const float*  __restrict__ evalv,
                            int E) {
    int gw   = (blockIdx.x * blockDim.x + threadIdx.x) >> 5;
    int lane = threadIdx.x & 31;
    int e0 = gw * EPW;
    if (e0 >= E) return;
    int e1 = min(e0 + EPW, E);

    float4 a0 = make_float4(0.f, 0.f, 0.f, 0.f);
    float4 a1 = make_float4(0.f, 0.f, 0.f, 0.f);
    int cur = __ldg(erow + e0);

#define ACC1(RR, VV, GG)                                                       \
    do {                                                                       \
        if ((RR) != cur) {                                                     \
            flush_row(cur, lane, a0, a1);                                      \
            a0 = make_float4(0.f, 0.f, 0.f, 0.f);                              \
            a1 = make_float4(0.f, 0.f, 0.f, 0.f);                              \
            cur = (RR);                                                        \
        }                                                                      \
        a0.x = fmaf((VV), (GG).x, a0.x);                                       \
        a0.y = fmaf((VV), (GG).y, a0.y);                                       \
        a0.z = fmaf((VV), (GG).z, a0.z);                                       \
        a0.w = fmaf((VV), (GG).w, a0.w);                                       \
        float vx = (VV) * (GG).x, vy = (VV) * (GG).y;                          \
        float vz = (VV) * (GG).z, vw = (VV) * (GG).w;                          \
        a1.x = fmaf(vx, (GG).x, a1.x);                                         \
        a1.y = fmaf(vy, (GG).y, a1.y);                                         \
        a1.z = fmaf(vz, (GG).z, a1.z);                                         \
        a1.w = fmaf(vw, (GG).w, a1.w);                                         \
    } while (0)

    int e = e0;
    for (; e + 4 <= e1; e += 4) {
        int4   r4 = *(const int4*)(erow + e);
        int4   c4 = *(const int4*)(ecol + e);
        float4 v4 = *(const float4*)(evalv + e);
        float4 g0 = __ldg(&x4[(size_t)c4.x * 32 + lane]);
        float4 g1 = __ldg(&x4[(size_t)c4.y * 32 + lane]);
        float4 g2 = __ldg(&x4[(size_t)c4.z * 32 + lane]);
        float4 g3 = __ldg(&x4[(size_t)c4.w * 32 + lane]);
        ACC1(r4.x, v4.x, g0);
        ACC1(r4.y, v4.y, g1);
        ACC1(r4.z, v4.z, g2);
        ACC1(r4.w, v4.w, g3);
    }
    for (; e < e1; ++e) {
        int   r = __ldg(erow + e);
        int   c = __ldg(ecol + e);
        float v = __ldg(evalv + e);
        float4 g = __ldg(&x4[(size_t)c * 32 + lane]);
        ACC1(r, v, g);
    }
    flush_row(cur, lane, a0, a1);
#undef ACC1
}

// ===========================================================================
// Kernel 3: mma.sync bf16 MLP (sm_80 ISA — works under compute_100).
// Per block: 128 rows x one branch. Split-bf16: D = Ah*Bh + Ah*Bl + Al*Bh,
// fp32 accum. A = h rows (K-contig, ldmatrix.x4). B = W as-is [k][n]
// (n-contig, ldmatrix.x4.trans). 8 warps, warp tile 32x64.
// ===========================================================================

#define STRB 272           // padded row stride in bytes (136 bf16)

__device__ __forceinline__ uint32_t smem_u32(const void* p) {
    uint32_t a;
    asm("{ .reg .u64 t; cvta.to.shared.u64 t, %1; cvt.u32.u64 %0, t; }"
        : "=r"(a) : "l"(p));
    return a;
}
__device__ __forceinline__ void ldmx4(uint32_t* r, uint32_t addr) {
    asm volatile("ldmatrix.sync.aligned.m8n8.x4.shared.b16 {%0,%1,%2,%3}, [%4];"
                 : "=r"(r[0]), "=r"(r[1]), "=r"(r[2]), "=r"(r[3]) : "r"(addr));
}
__device__ __forceinline__ void ldmx4t(uint32_t* r, uint32_t addr) {
    asm volatile("ldmatrix.sync.aligned.m8n8.x4.trans.shared.b16 {%0,%1,%2,%3}, [%4];"
                 : "=r"(r[0]), "=r"(r[1]), "=r"(r[2]), "=r"(r[3]) : "r"(addr));
}
__device__ __forceinline__ void mma16816(float* c, const uint32_t* a, const uint32_t* b) {
    asm volatile(
        "mma.sync.aligned.m16n8k16.row.col.f32.bf16.bf16.f32 "
        "{%0,%1,%2,%3}, {%4,%5,%6,%7}, {%8,%9}, {%0,%1,%2,%3};"
        : "+f"(c[0]), "+f"(c[1]), "+f"(c[2]), "+f"(c[3])
        : "r"(a[0]), "r"(a[1]), "r"(a[2]), "r"(a[3]), "r"(b[0]), "r"(b[1]));
}

__device__ __forceinline__ void split2(float x0, float x1, uint32_t& hi, uint32_t& lo) {
    __nv_bfloat16 h0 = __float2bfloat16_rn(x0);
    __nv_bfloat16 h1 = __float2bfloat16_rn(x1);
    __nv_bfloat16 l0 = __float2bfloat16_rn(x0 - __bfloat162float(h0));
    __nv_bfloat16 l1 = __float2bfloat16_rn(x1 - __bfloat162float(h1));
    hi = (uint32_t)__bfloat16_as_ushort(h0) | ((uint32_t)__bfloat16_as_ushort(h1) << 16);
    lo = (uint32_t)__bfloat16_as_ushort(l0) | ((uint32_t)__bfloat16_as_ushort(l1) << 16);
}

// SMEM byte offsets
#define TSZ (128 * STRB)          // 34816 per tile buffer
#define SM_AH 0
#define SM_AL (TSZ)
#define SM_BH (2 * TSZ)
#define SM_BL (3 * TSZ)
#define SM_B1S (4 * TSZ)          // float[128]
#define SM_B2S (4 * TSZ + 512)
#define SM_TOTAL (4 * TSZ + 1024) // 140288 B

// One GEMM layer: acc += split-bf16 product of A-tile and B-tile in smem.
__device__ __forceinline__ void mma_layer(uint32_t sb, int aHi, int aLo,
                                          int bHi, int bLo,
                                          float acc[2][8][4],
                                          int wm, int wn, int lane) {
    int arow = wm * 32 + (lane & 15);
    int akh  = 8 * (lane >> 4);
    int bkr  = (lane & 7) + 8 * ((lane >> 3) & 1);
    int bnc  = wn * 64 + 8 * (lane >> 4);

    #pragma unroll
    for (int p = 0; p < 3; ++p) {
        int aOff = (p == 2) ? aLo : aHi;
        int bOff = (p == 1) ? bLo : bHi;
        #pragma unroll
        for (int kc = 0; kc < 8; ++kc) {
            int k = kc * 16;
            uint32_t a[2][4];
            #pragma unroll
            for (int mt = 0; mt < 2; ++mt)
                ldmx4(a[mt], sb + aOff + (arow + mt * 16) * STRB + (k + akh) * 2);
            #pragma unroll
            for (int np = 0; np < 4; ++np) {
                uint32_t b[4];
                ldmx4t(b, sb + bOff + (k + bkr) * STRB + (bnc + np * 16) * 2);
                #pragma unroll
                for (int mt = 0; mt < 2; ++mt) {
                    mma16816(acc[mt][np * 2 + 0], a[mt], b + 0);
                    mma16816(acc[mt][np * 2 + 1], a[mt], b + 2);
                }
            }
        }
    }
}

__global__ void __launch_bounds__(256, 1)
mlp_mma_kernel(const float* __restrict__ W1, const float* __restrict__ b1,
               const float* __restrict__ W2, const float* __restrict__ b2,
               float* __restrict__ out, int n) {
    extern __shared__ char smem[];
    uint32_t sb = smem_u32(smem);
    int tid = threadIdx.x, wid = tid >> 5, lane = tid & 31;
    int wm = wid & 3, wn = wid >> 2;            // warp tile: rows 32*wm, cols 64*wn
    int g = lane >> 2, tg = lane & 3;           // mma C-frag coords
    int br = blockIdx.y;
    int r0 = blockIdx.x * 128;
    int rows = min(128, n - r0);
    const float* h  = (br ? g_h1 : g_h0) + (size_t)r0 * DD;
    const float* w1 = W1 + (size_t)br * DD * DD;
    const float* w2 = W2 + (size_t)br * DD * DD;

    if (tid < 128) {
        ((float*)(smem + SM_B1S))[tid] = __ldg(b1 + (size_t)br * DD + tid);
        ((float*)(smem + SM_B2S))[tid] = __ldg(b2 + (size_t)br * DD + tid);
    }

    // ---- A tile: h rows -> split bf16, row-major [row][k], stride 136 ----
    for (int i = tid; i < 128 * 32; i += 256) {
        int r = i >> 5, k = (i & 31) * 4;
        float4 v = (r < rows) ? __ldg((const float4*)(h + (size_t)r * DD + k))
                              : make_float4(0.f, 0.f, 0.f, 0.f);
        uint32_t hi0, lo0, hi1, lo1;
        split2(v.x, v.y, hi0, lo0);
        split2(v.z, v.w, hi1, lo1);
        char* pAH = smem + SM_AH + r * STRB + k * 2;
        char* pAL = smem + SM_AL + r * STRB + k * 2;
        *(uint32_t*)(pAH)     = hi0; *(uint32_t*)(pAH + 4) = hi1;
        *(uint32_t*)(pAL)     = lo0; *(uint32_t*)(pAL + 4) = lo1;
    }
    // ---- B tile: W1 as-is [k][n] -> split bf16, stride 136 ----
    for (int i = tid; i < 128 * 32; i += 256) {
        int k = i >> 5, nb = (i & 31) * 4;
        float4 v = __ldg((const float4*)(w1 + (size_t)k * DD + nb));
        uint32_t hi0, lo0, hi1, lo1;
        split2(v.x, v.y, hi0, lo0);
        split2(v.z, v.w, hi1, lo1);
        char* pBH = smem + SM_BH + k * STRB + nb * 2;
        char* pBL = smem + SM_BL + k * STRB + nb * 2;
        *(uint32_t*)(pBH)     = hi0; *(uint32_t*)(pBH + 4) = hi1;
        *(uint32_t*)(pBL)     = lo0; *(uint32_t*)(pBL + 4) = lo1;
    }
    __syncthreads();

    // ---- layer 1 ----
    float acc[2][8][4];
    #pragma unroll
    for (int mt = 0; mt < 2; ++mt)
        #pragma unroll
        for (int nt = 0; nt < 8; ++nt)
            #pragma unroll
            for (int j = 0; j < 4; ++j) acc[mt][nt][j] = 0.f;

    mma_layer(sb, SM_AH, SM_AL, SM_BH, SM_BL, acc, wm, wn, lane);
    __syncthreads();   // all reads of A/B done before T overwrites A

    // ---- epilogue 1: T = selu(acc + b1) -> re-split into A buffers ----
    {
        const float* b1s = (const float*)(smem + SM_B1S);
        #pragma unroll
        for (int mt = 0; mt < 2; ++mt) {
            int rbase = wm * 32 + mt * 16 + g;
            #pragma unroll
            for (int nt = 0; nt < 8; ++nt) {
                int col = wn * 64 + nt * 8 + 2 * tg;
                float bu = b1s[col], bv = b1s[col + 1];
                float f0 = selu_f(acc[mt][nt][0] + bu);
                float f1 = selu_f(acc[mt][nt][1] + bv);
                float f2 = selu_f(acc[mt][nt][2] + bu);
                float f3 = selu_f(acc[mt][nt][3] + bv);
                uint32_t hi, lo;
                split2(f0, f1, hi, lo);
                *(uint32_t*)(smem + SM_AH + rbase * STRB + col * 2) = hi;
                *(uint32_t*)(smem + SM_AL + rbase * STRB + col * 2) = lo;
                split2(f2, f3, hi, lo);
                *(uint32_t*)(smem + SM_AH + (rbase + 8) * STRB + col * 2) = hi;
                *(uint32_t*)(smem + SM_AL + (rbase + 8) * STRB + col * 2) = lo;
            }
        }
    }
    // ---- overwrite B with W2 (same phase) ----
    for (int i = tid; i < 128 * 32; i += 256) {
        int k = i >> 5, nb = (i & 31) * 4;
        float4 v = __ldg((const float4*)(w2 + (size_t)k * DD + nb));
        uint32_t hi0, lo0, hi1, lo1;
        split2(v.x, v.y, hi0, lo0);
        split2(v.z, v.w, hi1, lo1);
        char* pBH = smem + SM_BH + k * STRB + nb * 2;
        char* pBL = smem + SM_BL + k * STRB + nb * 2;
        *(uint32_t*)(pBH)     = hi0; *(uint32_t*)(pBH + 4) = hi1;
        *(uint32_t*)(pBL)     = lo0; *(uint32_t*)(pBL + 4) = lo1;
    }
    __syncthreads();

    // ---- layer 2 ----
    #pragma unroll
    for (int mt = 0; mt < 2; ++mt)
        #pragma unroll
        for (int nt = 0; nt < 8; ++nt)
            #pragma unroll
            for (int j = 0; j < 4; ++j) acc[mt][nt][j] = 0.f;

    mma_layer(sb, SM_AH, SM_AL, SM_BH, SM_BL, acc, wm, wn, lane);

    // ---- epilogue 2: out = selu(acc + b2) -> gmem ----
    {
        const float* b2s = (const float*)(smem + SM_B2S);
        #pragma unroll
        for (int mt = 0; mt < 2; ++mt) {
            int rbase = wm * 32 + mt * 16 + g;
            #pragma unroll
            for (int nt = 0; nt < 8; ++nt) {
                int col = wn * 64 + nt * 8 + 2 * tg;
                float bu = b2s[col], bv = b2s[col + 1];
                if (rbase < rows) {
                    float2 o;
                    o.x = selu_f(acc[mt][nt][0] + bu);
                    o.y = selu_f(acc[mt][nt][1] + bv);
                    *(float2*)(out + (size_t)(r0 + rbase) * (2 * DD) + br * DD + col) = o;
                }
                if (rbase + 8 < rows) {
                    float2 o;
                    o.x = selu_f(acc[mt][nt][2] + bu);
                    o.y = selu_f(acc[mt][nt][3] + bv);
                    *(float2*)(out + (size_t)(r0 + rbase + 8) * (2 * DD) + br * DD + col) = o;
                }
            }
        }
    }
}

// ---------------------------------------------------------------------------
extern "C" void kernel_launch(void* const* d_in, const int* in_sizes, int n_in,
                              void* d_out, int out_size) {
    const float* x_in  = (const float*)d_in[0];
    const int*   erow  = (const int*)d_in[1];
    const int*   ecol  = (const int*)d_in[2];
    const float* evalv = (const float*)d_in[3];
    const float* W1 = (const float*)d_in[4];
    const float* b1 = (const float*)d_in[5];
    const float* W2 = (const float*)d_in[6];
    const float* b2 = (const float*)d_in[7];
    float* out = (float*)d_out;

    int n = in_sizes[0] / DD;      // 100000
    int E = in_sizes[1];           // 1600000

    int n4 = n * DD / 4;
    init_h_kernel<<<(n4 + 255) / 256, 256>>>((const float4*)x_in, n4);

    int warps = (E + EPW - 1) / EPW;
    int sblocks = (warps * 32 + 255) / 256;
    spmm_kernel<<<sblocks, 256>>>((const float4*)x_in, erow, ecol, evalv, E);

    cudaFuncSetAttribute(mlp_mma_kernel, cudaFuncAttributeMaxDynamicSharedMemorySize, SM_TOTAL);
    dim3 grid((n + 127) / 128, 2);
    mlp_mma_kernel<<<grid, 256, SM_TOTAL>>>(W1, b1, W2, b2, out, n);
}

// round 13
// speedup vs baseline: 1.2987x; 1.0297x over previous
#include <cuda_runtime.h>
#include <cuda_bf16.h>
#include <cstdint>

#define NN 100000
#define DD 128
#define EPW 64            // edges per warp in spmm

#define SELU_SCALE 1.0507009873554805f
#define SELU_ALPHA 1.6732632423543772f

// Scratch: h_i = spmm(x_in^(i+1)) + x_in^(i+1)   (residual folded into init)
__device__ float g_h0[NN * DD];
__device__ float g_h1[NN * DD];

__device__ __forceinline__ float selu_f(float x) {
    return x > 0.f ? SELU_SCALE * x
                   : (SELU_SCALE * SELU_ALPHA) * (__expf(x) - 1.f);
}

// ---------------------------------------------------------------------------
// Kernel 1: h0 = x_in ; h1 = x_in * x_in   (residual pre-init)
// ---------------------------------------------------------------------------
__global__ void init_h_kernel(const float4* __restrict__ x4, int n4) {
    int i = blockIdx.x * blockDim.x + threadIdx.x;
    if (i >= n4) return;
    float4 v = __ldg(&x4[i]);
    ((float4*)g_h0)[i] = v;
    ((float4*)g_h1)[i] = make_float4(v.x * v.x, v.y * v.y, v.z * v.z, v.w * v.w);
}

// ---------------------------------------------------------------------------
// Kernel 2: fused dual-branch SpMM, 4-edge batched gathers (unchanged)
// ---------------------------------------------------------------------------
__device__ __forceinline__ void flush_row(int r, int lane,
                                          const float4& a0, const float4& a1) {
    float* p0 = g_h0 + (size_t)r * DD + lane * 4;
    float* p1 = g_h1 + (size_t)r * DD + lane * 4;
    atomicAdd(p0 + 0, a0.x); atomicAdd(p0 + 1, a0.y);
    atomicAdd(p0 + 2, a0.z); atomicAdd(p0 + 3, a0.w);
    atomicAdd(p1 + 0, a1.x); atomicAdd(p1 + 1, a1.y);
    atomicAdd(p1 + 2, a1.z); atomicAdd(p1 + 3, a1.w);
}

__global__ void spmm_kernel(const float4* __restrict__ x4,
                            const int*    __restrict__ erow,
                            const int*    __restrict__ ecol,
                            const float*  __restrict__ evalv,
                            int E) {
    int gw   = (blockIdx.x * blockDim.x + threadIdx.x) >> 5;
    int lane = threadIdx.x & 31;
    int e0 = gw * EPW;
    if (e0 >= E) return;
    int e1 = min(e0 + EPW, E);

    float4 a0 = make_float4(0.f, 0.f, 0.f, 0.f);
    float4 a1 = make_float4(0.f, 0.f, 0.f, 0.f);
    int cur = __ldg(erow + e0);

#define ACC1(RR, VV, GG)                                                       \
    do {                                                                       \
        if ((RR) != cur) {                                                     \
            flush_row(cur, lane, a0, a1);                                      \
            a0 = make_float4(0.f, 0.f, 0.f, 0.f);                              \
            a1 = make_float4(0.f, 0.f, 0.f, 0.f);                              \
            cur = (RR);                                                        \
        }                                                                      \
        a0.x = fmaf((VV), (GG).x, a0.x);                                       \
        a0.y = fmaf((VV), (GG).y, a0.y);                                       \
        a0.z = fmaf((VV), (GG).z, a0.z);                                       \
        a0.w = fmaf((VV), (GG).w, a0.w);                                       \
        float vx = (VV) * (GG).x, vy = (VV) * (GG).y;                          \
        float vz = (VV) * (GG).z, vw = (VV) * (GG).w;                          \
        a1.x = fmaf(vx, (GG).x, a1.x);                                         \
        a1.y = fmaf(vy, (GG).y, a1.y);                                         \
        a1.z = fmaf(vz, (GG).z, a1.z);                                         \
        a1.w = fmaf(vw, (GG).w, a1.w);                                         \
    } while (0)

    int e = e0;
    for (; e + 4 <= e1; e += 4) {
        int4   r4 = *(const int4*)(erow + e);
        int4   c4 = *(const int4*)(ecol + e);
        float4 v4 = *(const float4*)(evalv + e);
        float4 g0 = __ldg(&x4[(size_t)c4.x * 32 + lane]);
        float4 g1 = __ldg(&x4[(size_t)c4.y * 32 + lane]);
        float4 g2 = __ldg(&x4[(size_t)c4.z * 32 + lane]);
        float4 g3 = __ldg(&x4[(size_t)c4.w * 32 + lane]);
        ACC1(r4.x, v4.x, g0);
        ACC1(r4.y, v4.y, g1);
        ACC1(r4.z, v4.z, g2);
        ACC1(r4.w, v4.w, g3);
    }
    for (; e < e1; ++e) {
        int   r = __ldg(erow + e);
        int   c = __ldg(ecol + e);
        float v = __ldg(evalv + e);
        float4 g = __ldg(&x4[(size_t)c * 32 + lane]);
        ACC1(r, v, g);
    }
    flush_row(cur, lane, a0, a1);
#undef ACC1
}

// ===========================================================================
// Kernel 3: mma.sync bf16 MLP — identical to the 535us-passing R7 kernel
// except the mainloop is deduped: each A/B fragment is ldmatrix'd ONCE
// (96 ldmatrix per layer-warp instead of 144), mma count unchanged.
// ===========================================================================

#define STRB 272           // padded row stride in bytes (136 bf16)

__device__ __forceinline__ uint32_t smem_u32(const void* p) {
    uint32_t a;
    asm("{ .reg .u64 t; cvta.to.shared.u64 t, %1; cvt.u32.u64 %0, t; }"
        : "=r"(a) : "l"(p));
    return a;
}
__device__ __forceinline__ void ldmx4(uint32_t* r, uint32_t addr) {
    asm volatile("ldmatrix.sync.aligned.m8n8.x4.shared.b16 {%0,%1,%2,%3}, [%4];"
                 : "=r"(r[0]), "=r"(r[1]), "=r"(r[2]), "=r"(r[3]) : "r"(addr));
}
__device__ __forceinline__ void ldmx4t(uint32_t* r, uint32_t addr) {
    asm volatile("ldmatrix.sync.aligned.m8n8.x4.trans.shared.b16 {%0,%1,%2,%3}, [%4];"
                 : "=r"(r[0]), "=r"(r[1]), "=r"(r[2]), "=r"(r[3]) : "r"(addr));
}
__device__ __forceinline__ void mma16816(float* c, const uint32_t* a, const uint32_t* b) {
    asm volatile(
        "mma.sync.aligned.m16n8k16.row.col.f32.bf16.bf16.f32 "
        "{%0,%1,%2,%3}, {%4,%5,%6,%7}, {%8,%9}, {%0,%1,%2,%3};"
        : "+f"(c[0]), "+f"(c[1]), "+f"(c[2]), "+f"(c[3])
        : "r"(a[0]), "r"(a[1]), "r"(a[2]), "r"(a[3]), "r"(b[0]), "r"(b[1]));
}

__device__ __forceinline__ void split2(float x0, float x1, uint32_t& hi, uint32_t& lo) {
    __nv_bfloat16 h0 = __float2bfloat16_rn(x0);
    __nv_bfloat16 h1 = __float2bfloat16_rn(x1);
    __nv_bfloat16 l0 = __float2bfloat16_rn(x0 - __bfloat162float(h0));
    __nv_bfloat16 l1 = __float2bfloat16_rn(x1 - __bfloat162float(h1));
    hi = (uint32_t)__bfloat16_as_ushort(h0) | ((uint32_t)__bfloat16_as_ushort(h1) << 16);
    lo = (uint32_t)__bfloat16_as_ushort(l0) | ((uint32_t)__bfloat16_as_ushort(l1) << 16);
}

// SMEM byte offsets (identical to passing R7: ~140 KB)
#define TSZ (128 * STRB)          // 34816
#define SM_AH 0
#define SM_AL (TSZ)
#define SM_BH (2 * TSZ)
#define SM_BL (3 * TSZ)
#define SM_B1S (4 * TSZ)          // float[128]
#define SM_B2S (4 * TSZ + 512)
#define SM_TOTAL (4 * TSZ + 1024) // 140288 B

// Deduped GEMM layer for a 32x64 warp tile (8 warps: wm 0..3, wn 0..1).
// Per k-chunk: ah/al loaded once; per 16-col pair: bh/bl loaded once; then
// the 3 split products (Ah*Bh + Ah*Bl + Al*Bh) issue from registers.
__device__ __forceinline__ void mma_layer(uint32_t sb, int aHi, int aLo,
                                          int bHi, int bLo,
                                          float acc[2][8][4],
                                          int wm, int wn, int lane) {
    int arow = wm * 32 + (lane & 15);
    int akh  = 8 * (lane >> 4);
    int bkr  = (lane & 7) + 8 * ((lane >> 3) & 1);
    int bnc  = wn * 64 + 8 * (lane >> 4);

    #pragma unroll
    for (int kc = 0; kc < 8; ++kc) {
        int k = kc * 16;
        uint32_t ah[2][4], al[2][4];
        #pragma unroll
        for (int mt = 0; mt < 2; ++mt) {
            ldmx4(ah[mt], sb + aHi + (arow + mt * 16) * STRB + (k + akh) * 2);
            ldmx4(al[mt], sb + aLo + (arow + mt * 16) * STRB + (k + akh) * 2);
        }
        #pragma unroll
        for (int np = 0; np < 4; ++np) {
            uint32_t bh[4], bl[4];
            ldmx4t(bh, sb + bHi + (k + bkr) * STRB + (bnc + np * 16) * 2);
            ldmx4t(bl, sb + bLo + (k + bkr) * STRB + (bnc + np * 16) * 2);
            #pragma unroll
            for (int mt = 0; mt < 2; ++mt) {
                #pragma unroll
                for (int hh = 0; hh < 2; ++hh) {
                    float* c = acc[mt][np * 2 + hh];
                    mma16816(c, ah[mt], bh + 2 * hh);
                    mma16816(c, ah[mt], bl + 2 * hh);
                    mma16816(c, al[mt], bh + 2 * hh);
                }
            }
        }
    }
}

__global__ void __launch_bounds__(256, 1)
mlp_mma_kernel(const float* __restrict__ W1, const float* __restrict__ b1,
               const float* __restrict__ W2, const float* __restrict__ b2,
               float* __restrict__ out, int n) {
    extern __shared__ char smem[];
    uint32_t sb = smem_u32(smem);
    int tid = threadIdx.x, wid = tid >> 5, lane = tid & 31;
    int wm = wid & 3, wn = wid >> 2;            // warp tile: rows 32*wm, cols 64*wn
    int g = lane >> 2, tg = lane & 3;           // mma C-frag coords
    int br = blockIdx.y;
    int r0 = blockIdx.x * 128;
    int rows = min(128, n - r0);
    const float* h  = (br ? g_h1 : g_h0) + (size_t)r0 * DD;
    const float* w1 = W1 + (size_t)br * DD * DD;
    const float* w2 = W2 + (size_t)br * DD * DD;

    if (tid < 128) {
        ((float*)(smem + SM_B1S))[tid] = __ldg(b1 + (size_t)br * DD + tid);
        ((float*)(smem + SM_B2S))[tid] = __ldg(b2 + (size_t)br * DD + tid);
    }

    // ---- A tile: h rows -> split bf16, row-major [row][k], stride 136 ----
    for (int i = tid; i < 128 * 32; i += 256) {
        int r = i >> 5, k = (i & 31) * 4;
        float4 v = (r < rows) ? __ldg((const float4*)(h + (size_t)r * DD + k))
                              : make_float4(0.f, 0.f, 0.f, 0.f);
        uint32_t hi0, lo0, hi1, lo1;
        split2(v.x, v.y, hi0, lo0);
        split2(v.z, v.w, hi1, lo1);
        char* pAH = smem + SM_AH + r * STRB + k * 2;
        char* pAL = smem + SM_AL + r * STRB + k * 2;
        *(uint32_t*)(pAH)     = hi0; *(uint32_t*)(pAH + 4) = hi1;
        *(uint32_t*)(pAL)     = lo0; *(uint32_t*)(pAL + 4) = lo1;
    }
    // ---- B tile: W1 as-is [k][n] -> split bf16, stride 136 ----
    for (int i = tid; i < 128 * 32; i += 256) {
        int k = i >> 5, nb = (i & 31) * 4;
        float4 v = __ldg((const float4*)(w1 + (size_t)k * DD + nb));
        uint32_t hi0, lo0, hi1, lo1;
        split2(v.x, v.y, hi0, lo0);
        split2(v.z, v.w, hi1, lo1);
        char* pBH = smem + SM_BH + k * STRB + nb * 2;
        char* pBL = smem + SM_BL + k * STRB + nb * 2;
        *(uint32_t*)(pBH)     = hi0; *(uint32_t*)(pBH + 4) = hi1;
        *(uint32_t*)(pBL)     = lo0; *(uint32_t*)(pBL + 4) = lo1;
    }
    __syncthreads();

    // ---- layer 1 ----
    float acc[2][8][4];
    #pragma unroll
    for (int mt = 0; mt < 2; ++mt)
        #pragma unroll
        for (int nt = 0; nt < 8; ++nt)
            #pragma unroll
            for (int j = 0; j < 4; ++j) acc[mt][nt][j] = 0.f;

    mma_layer(sb, SM_AH, SM_AL, SM_BH, SM_BL, acc, wm, wn, lane);
    __syncthreads();   // all reads of A/B done before T overwrites A

    // ---- epilogue 1: T = selu(acc + b1) -> re-split into A buffers ----
    {
        const float* b1s = (const float*)(smem + SM_B1S);
        #pragma unroll
        for (int mt = 0; mt < 2; ++mt) {
            int rbase = wm * 32 + mt * 16 + g;
            #pragma unroll
            for (int nt = 0; nt < 8; ++nt) {
                int col = wn * 64 + nt * 8 + 2 * tg;
                float bu = b1s[col], bv = b1s[col + 1];
                float f0 = selu_f(acc[mt][nt][0] + bu);
                float f1 = selu_f(acc[mt][nt][1] + bv);
                float f2 = selu_f(acc[mt][nt][2] + bu);
                float f3 = selu_f(acc[mt][nt][3] + bv);
                uint32_t hi, lo;
                split2(f0, f1, hi, lo);
                *(uint32_t*)(smem + SM_AH + rbase * STRB + col * 2) = hi;
                *(uint32_t*)(smem + SM_AL + rbase * STRB + col * 2) = lo;
                split2(f2, f3, hi, lo);
                *(uint32_t*)(smem + SM_AH + (rbase + 8) * STRB + col * 2) = hi;
                *(uint32_t*)(smem + SM_AL + (rbase + 8) * STRB + col * 2) = lo;
            }
        }
    }
    // ---- overwrite B with W2 (same phase) ----
    for (int i = tid; i < 128 * 32; i += 256) {
        int k = i >> 5, nb = (i & 31) * 4;
        float4 v = __ldg((const float4*)(w2 + (size_t)k * DD + nb));
        uint32_t hi0, lo0, hi1, lo1;
        split2(v.x, v.y, hi0, lo0);
        split2(v.z, v.w, hi1, lo1);
        char* pBH = smem + SM_BH + k * STRB + nb * 2;
        char* pBL = smem + SM_BL + k * STRB + nb * 2;
        *(uint32_t*)(pBH)     = hi0; *(uint32_t*)(pBH + 4) = hi1;
        *(uint32_t*)(pBL)     = lo0; *(uint32_t*)(pBL + 4) = lo1;
    }
    __syncthreads();

    // ---- layer 2 ----
    #pragma unroll
    for (int mt = 0; mt < 2; ++mt)
        #pragma unroll
        for (int nt = 0; nt < 8; ++nt)
            #pragma unroll
            for (int j = 0; j < 4; ++j) acc[mt][nt][j] = 0.f;

    mma_layer(sb, SM_AH, SM_AL, SM_BH, SM_BL, acc, wm, wn, lane);

    // ---- epilogue 2: out = selu(acc + b2) -> gmem ----
    {
        const float* b2s = (const float*)(smem + SM_B2S);
        #pragma unroll
        for (int mt = 0; mt < 2; ++mt) {
            int rbase = wm * 32 + mt * 16 + g;
            #pragma unroll
            for (int nt = 0; nt < 8; ++nt) {
                int col = wn * 64 + nt * 8 + 2 * tg;
                float bu = b2s[col], bv = b2s[col + 1];
                if (rbase < rows) {
                    float2 o;
                    o.x = selu_f(acc[mt][nt][0] + bu);
                    o.y = selu_f(acc[mt][nt][1] + bv);
                    *(float2*)(out + (size_t)(r0 + rbase) * (2 * DD) + br * DD + col) = o;
                }
                if (rbase + 8 < rows) {
                    float2 o;
                    o.x = selu_f(acc[mt][nt][2] + bu);
                    o.y = selu_f(acc[mt][nt][3] + bv);
                    *(float2*)(out + (size_t)(r0 + rbase + 8) * (2 * DD) + br * DD + col) = o;
                }
            }
        }
    }
}

// ---------------------------------------------------------------------------
extern "C" void kernel_launch(void* const* d_in, const int* in_sizes, int n_in,
                              void* d_out, int out_size) {
    const float* x_in  = (const float*)d_in[0];
    const int*   erow  = (const int*)d_in[1];
    const int*   ecol  = (const int*)d_in[2];
    const float* evalv = (const float*)d_in[3];
    const float* W1 = (const float*)d_in[4];
    const float* b1 = (const float*)d_in[5];
    const float* W2 = (const float*)d_in[6];
    const float* b2 = (const float*)d_in[7];
    float* out = (float*)d_out;

    int n = in_sizes[0] / DD;      // 100000
    int E = in_sizes[1];           // 1600000

    int n4 = n * DD / 4;
    init_h_kernel<<<(n4 + 255) / 256, 256>>>((const float4*)x_in, n4);

    int warps = (E + EPW - 1) / EPW;
    int sblocks = (warps * 32 + 255) / 256;
    spmm_kernel<<<sblocks, 256>>>((const float4*)x_in, erow, ecol, evalv, E);

    cudaFuncSetAttribute(mlp_mma_kernel, cudaFuncAttributeMaxDynamicSharedMemorySize, SM_TOTAL);
    dim3 grid((n + 127) / 128, 2);
    mlp_mma_kernel<<<grid, 256, SM_TOTAL>>>(W1, b1, W2, b2, out, n);
}

// round 14
// speedup vs baseline: 1.7446x; 1.3433x over previous
#include <cuda_runtime.h>
#include <cuda_bf16.h>
#include <cstdint>

#define NN 100000
#define DD 128
#define EPW 64            // edges per warp in spmm

#define SELU_SCALE 1.0507009873554805f
#define SELU_ALPHA 1.6732632423543772f

// Scratch: h_i = spmm(x_in^(i+1)) + x_in^(i+1)   (residual folded into init)
__device__ float g_h0[NN * DD];
__device__ float g_h1[NN * DD];

__device__ __forceinline__ float selu_f(float x) {
    return x > 0.f ? SELU_SCALE * x
                   : (SELU_SCALE * SELU_ALPHA) * (__expf(x) - 1.f);
}

// ---------------------------------------------------------------------------
// Kernel 1: h0 = x_in ; h1 = x_in * x_in   (residual pre-init)
// ---------------------------------------------------------------------------
__global__ void init_h_kernel(const float4* __restrict__ x4, int n4) {
    int i = blockIdx.x * blockDim.x + threadIdx.x;
    if (i >= n4) return;
    float4 v = __ldg(&x4[i]);
    ((float4*)g_h0)[i] = v;
    ((float4*)g_h1)[i] = make_float4(v.x * v.x, v.y * v.y, v.z * v.z, v.w * v.w);
}

// ---------------------------------------------------------------------------
// Kernel 2: fused dual-branch SpMM, 4-edge batched gathers (unchanged)
// ---------------------------------------------------------------------------
__device__ __forceinline__ void flush_row(int r, int lane,
                                          const float4& a0, const float4& a1) {
    float* p0 = g_h0 + (size_t)r * DD + lane * 4;
    float* p1 = g_h1 + (size_t)r * DD + lane * 4;
    atomicAdd(p0 + 0, a0.x); atomicAdd(p0 + 1, a0.y);
    atomicAdd(p0 + 2, a0.z); atomicAdd(p0 + 3, a0.w);
    atomicAdd(p1 + 0, a1.x); atomicAdd(p1 + 1, a1.y);
    atomicAdd(p1 + 2, a1.z); atomicAdd(p1 + 3, a1.w);
}

__global__ void spmm_kernel(const float4* __restrict__ x4,
                            const int*    __restrict__ erow,
                            const int*    __restrict__ ecol,
                            const float*  __restrict__ evalv,
                            int E) {
    int gw   = (blockIdx.x * blockDim.x + threadIdx.x) >> 5;
    int lane = threadIdx.x & 31;
    int e0 = gw * EPW;
    if (e0 >= E) return;
    int e1 = min(e0 + EPW, E);

    float4 a0 = make_float4(0.f, 0.f, 0.f, 0.f);
    float4 a1 = make_float4(0.f, 0.f, 0.f, 0.f);
    int cur = __ldg(erow + e0);

#define ACC1(RR, VV, GG)                                                       \
    do {                                                                       \
        if ((RR) != cur) {                                                     \
            flush_row(cur, lane, a0, a1);                                      \
            a0 = make_float4(0.f, 0.f, 0.f, 0.f);                              \
            a1 = make_float4(0.f, 0.f, 0.f, 0.f);                              \
            cur = (RR);                                                        \
        }                                                                      \
        a0.x = fmaf((VV), (GG).x, a0.x);                                       \
        a0.y = fmaf((VV), (GG).y, a0.y);                                       \
        a0.z = fmaf((VV), (GG).z, a0.z);                                       \
        a0.w = fmaf((VV), (GG).w, a0.w);                                       \
        float vx = (VV) * (GG).x, vy = (VV) * (GG).y;                          \
        float vz = (VV) * (GG).z, vw = (VV) * (GG).w;                          \
        a1.x = fmaf(vx, (GG).x, a1.x);                                         \
        a1.y = fmaf(vy, (GG).y, a1.y);                                         \
        a1.z = fmaf(vz, (GG).z, a1.z);                                         \
        a1.w = fmaf(vw, (GG).w, a1.w);                                         \
    } while (0)

    int e = e0;
    for (; e + 4 <= e1; e += 4) {
        int4   r4 = *(const int4*)(erow + e);
        int4   c4 = *(const int4*)(ecol + e);
        float4 v4 = *(const float4*)(evalv + e);
        float4 g0 = __ldg(&x4[(size_t)c4.x * 32 + lane]);
        float4 g1 = __ldg(&x4[(size_t)c4.y * 32 + lane]);
        float4 g2 = __ldg(&x4[(size_t)c4.z * 32 + lane]);
        float4 g3 = __ldg(&x4[(size_t)c4.w * 32 + lane]);
        ACC1(r4.x, v4.x, g0);
        ACC1(r4.y, v4.y, g1);
        ACC1(r4.z, v4.z, g2);
        ACC1(r4.w, v4.w, g3);
    }
    for (; e < e1; ++e) {
        int   r = __ldg(erow + e);
        int   c = __ldg(ecol + e);
        float v = __ldg(evalv + e);
        float4 g = __ldg(&x4[(size_t)c * 32 + lane]);
        ACC1(r, v, g);
    }
    flush_row(cur, lane, a0, a1);
#undef ACC1
}

// ===========================================================================
// Kernel 3: mma.sync bf16 MLP — R13 structure with 512 threads (16 warps,
// 4x4 grid of 32x32 warp tiles). Same smem map, same deduped mainloop.
// ===========================================================================

#define STRB 272           // padded row stride in bytes (136 bf16)
#define MLPT 512

__device__ __forceinline__ uint32_t smem_u32(const void* p) {
    uint32_t a;
    asm("{ .reg .u64 t; cvta.to.shared.u64 t, %1; cvt.u32.u64 %0, t; }"
        : "=r"(a) : "l"(p));
    return a;
}
__device__ __forceinline__ void ldmx4(uint32_t* r, uint32_t addr) {
    asm volatile("ldmatrix.sync.aligned.m8n8.x4.shared.b16 {%0,%1,%2,%3}, [%4];"
                 : "=r"(r[0]), "=r"(r[1]), "=r"(r[2]), "=r"(r[3]) : "r"(addr));
}
__device__ __forceinline__ void ldmx4t(uint32_t* r, uint32_t addr) {
    asm volatile("ldmatrix.sync.aligned.m8n8.x4.trans.shared.b16 {%0,%1,%2,%3}, [%4];"
                 : "=r"(r[0]), "=r"(r[1]), "=r"(r[2]), "=r"(r[3]) : "r"(addr));
}
__device__ __forceinline__ void mma16816(float* c, const uint32_t* a, const uint32_t* b) {
    asm volatile(
        "mma.sync.aligned.m16n8k16.row.col.f32.bf16.bf16.f32 "
        "{%0,%1,%2,%3}, {%4,%5,%6,%7}, {%8,%9}, {%0,%1,%2,%3};"
        : "+f"(c[0]), "+f"(c[1]), "+f"(c[2]), "+f"(c[3])
        : "r"(a[0]), "r"(a[1]), "r"(a[2]), "r"(a[3]), "r"(b[0]), "r"(b[1]));
}

__device__ __forceinline__ void split2(float x0, float x1, uint32_t& hi, uint32_t& lo) {
    __nv_bfloat16 h0 = __float2bfloat16_rn(x0);
    __nv_bfloat16 h1 = __float2bfloat16_rn(x1);
    __nv_bfloat16 l0 = __float2bfloat16_rn(x0 - __bfloat162float(h0));
    __nv_bfloat16 l1 = __float2bfloat16_rn(x1 - __bfloat162float(h1));
    hi = (uint32_t)__bfloat16_as_ushort(h0) | ((uint32_t)__bfloat16_as_ushort(h1) << 16);
    lo = (uint32_t)__bfloat16_as_ushort(l0) | ((uint32_t)__bfloat16_as_ushort(l1) << 16);
}

// SMEM byte offsets (identical to passing R13: ~140 KB)
#define TSZ (128 * STRB)          // 34816
#define SM_AH 0
#define SM_AL (TSZ)
#define SM_BH (2 * TSZ)
#define SM_BL (3 * TSZ)
#define SM_B1S (4 * TSZ)          // float[128]
#define SM_B2S (4 * TSZ + 512)
#define SM_TOTAL (4 * TSZ + 1024) // 140288 B

// Deduped GEMM layer for a 32x32 warp tile (16 warps: wm 0..3, wn 0..3).
__device__ __forceinline__ void mma_layer(uint32_t sb, int aHi, int aLo,
                                          int bHi, int bLo,
                                          float acc[2][4][4],
                                          int wm, int wn, int lane) {
    int arow = wm * 32 + (lane & 15);
    int akh  = 8 * (lane >> 4);
    int bkr  = (lane & 7) + 8 * ((lane >> 3) & 1);
    int bnc  = wn * 32 + 8 * (lane >> 4);

    #pragma unroll
    for (int kc = 0; kc < 8; ++kc) {
        int k = kc * 16;
        uint32_t ah[2][4], al[2][4];
        #pragma unroll
        for (int mt = 0; mt < 2; ++mt) {
            ldmx4(ah[mt], sb + aHi + (arow + mt * 16) * STRB + (k + akh) * 2);
            ldmx4(al[mt], sb + aLo + (arow + mt * 16) * STRB + (k + akh) * 2);
        }
        #pragma unroll
        for (int np = 0; np < 2; ++np) {
            uint32_t bh[4], bl[4];
            ldmx4t(bh, sb + bHi + (k + bkr) * STRB + (bnc + np * 16) * 2);
            ldmx4t(bl, sb + bLo + (k + bkr) * STRB + (bnc + np * 16) * 2);
            #pragma unroll
            for (int mt = 0; mt < 2; ++mt) {
                #pragma unroll
                for (int hh = 0; hh < 2; ++hh) {
                    float* c = acc[mt][np * 2 + hh];
                    mma16816(c, ah[mt], bh + 2 * hh);
                    mma16816(c, ah[mt], bl + 2 * hh);
                    mma16816(c, al[mt], bh + 2 * hh);
                }
            }
        }
    }
}

__global__ void __launch_bounds__(MLPT, 1)
mlp_mma_kernel(const float* __restrict__ W1, const float* __restrict__ b1,
               const float* __restrict__ W2, const float* __restrict__ b2,
               float* __restrict__ out, int n) {
    extern __shared__ char smem[];
    uint32_t sb = smem_u32(smem);
    int tid = threadIdx.x, wid = tid >> 5, lane = tid & 31;
    int wm = wid & 3, wn = wid >> 2;            // 4x4 warp grid, 32x32 tiles
    int g = lane >> 2, tg = lane & 3;           // mma C-frag coords
    int br = blockIdx.y;
    int r0 = blockIdx.x * 128;
    int rows = min(128, n - r0);
    const float* h  = (br ? g_h1 : g_h0) + (size_t)r0 * DD;
    const float* w1 = W1 + (size_t)br * DD * DD;
    const float* w2 = W2 + (size_t)br * DD * DD;

    if (tid < 128) {
        ((float*)(smem + SM_B1S))[tid] = __ldg(b1 + (size_t)br * DD + tid);
        ((float*)(smem + SM_B2S))[tid] = __ldg(b2 + (size_t)br * DD + tid);
    }

    // ---- A tile: h rows -> split bf16, row-major [row][k], stride 136 ----
    for (int i = tid; i < 128 * 32; i += MLPT) {
        int r = i >> 5, k = (i & 31) * 4;
        float4 v = (r < rows) ? __ldg((const float4*)(h + (size_t)r * DD + k))
                              : make_float4(0.f, 0.f, 0.f, 0.f);
        uint32_t hi0, lo0, hi1, lo1;
        split2(v.x, v.y, hi0, lo0);
        split2(v.z, v.w, hi1, lo1);
        char* pAH = smem + SM_AH + r * STRB + k * 2;
        char* pAL = smem + SM_AL + r * STRB + k * 2;
        *(uint32_t*)(pAH)     = hi0; *(uint32_t*)(pAH + 4) = hi1;
        *(uint32_t*)(pAL)     = lo0; *(uint32_t*)(pAL + 4) = lo1;
    }
    // ---- B tile: W1 as-is [k][n] -> split bf16, stride 136 ----
    for (int i = tid; i < 128 * 32; i += MLPT) {
        int k = i >> 5, nb = (i & 31) * 4;
        float4 v = __ldg((const float4*)(w1 + (size_t)k * DD + nb));
        uint32_t hi0, lo0, hi1, lo1;
        split2(v.x, v.y, hi0, lo0);
        split2(v.z, v.w, hi1, lo1);
        char* pBH = smem + SM_BH + k * STRB + nb * 2;
        char* pBL = smem + SM_BL + k * STRB + nb * 2;
        *(uint32_t*)(pBH)     = hi0; *(uint32_t*)(pBH + 4) = hi1;
        *(uint32_t*)(pBL)     = lo0; *(uint32_t*)(pBL + 4) = lo1;
    }
    __syncthreads();

    // ---- layer 1 ----
    float acc[2][4][4];
    #pragma unroll
    for (int mt = 0; mt < 2; ++mt)
        #pragma unroll
        for (int nt = 0; nt < 4; ++nt)
            #pragma unroll
            for (int j = 0; j < 4; ++j) acc[mt][nt][j] = 0.f;

    mma_layer(sb, SM_AH, SM_AL, SM_BH, SM_BL, acc, wm, wn, lane);
    __syncthreads();   // all reads of A/B done before T overwrites A

    // ---- epilogue 1: T = selu(acc + b1) -> re-split into A buffers ----
    {
        const float* b1s = (const float*)(smem + SM_B1S);
        #pragma unroll
        for (int mt = 0; mt < 2; ++mt) {
            int rbase = wm * 32 + mt * 16 + g;
            #pragma unroll
            for (int nt = 0; nt < 4; ++nt) {
                int col = wn * 32 + nt * 8 + 2 * tg;
                float bu = b1s[col], bv = b1s[col + 1];
                float f0 = selu_f(acc[mt][nt][0] + bu);
                float f1 = selu_f(acc[mt][nt][1] + bv);
                float f2 = selu_f(acc[mt][nt][2] + bu);
                float f3 = selu_f(acc[mt][nt][3] + bv);
                uint32_t hi, lo;
                split2(f0, f1, hi, lo);
                *(uint32_t*)(smem + SM_AH + rbase * STRB + col * 2) = hi;
                *(uint32_t*)(smem + SM_AL + rbase * STRB + col * 2) = lo;
                split2(f2, f3, hi, lo);
                *(uint32_t*)(smem + SM_AH + (rbase + 8) * STRB + col * 2) = hi;
                *(uint32_t*)(smem + SM_AL + (rbase + 8) * STRB + col * 2) = lo;
            }
        }
    }
    // ---- overwrite B with W2 (same phase) ----
    for (int i = tid; i < 128 * 32; i += MLPT) {
        int k = i >> 5, nb = (i & 31) * 4;
        float4 v = __ldg((const float4*)(w2 + (size_t)k * DD + nb));
        uint32_t hi0, lo0, hi1, lo1;
        split2(v.x, v.y, hi0, lo0);
        split2(v.z, v.w, hi1, lo1);
        char* pBH = smem + SM_BH + k * STRB + nb * 2;
        char* pBL = smem + SM_BL + k * STRB + nb * 2;
        *(uint32_t*)(pBH)     = hi0; *(uint32_t*)(pBH + 4) = hi1;
        *(uint32_t*)(pBL)     = lo0; *(uint32_t*)(pBL + 4) = lo1;
    }
    __syncthreads();

    // ---- layer 2 ----
    #pragma unroll
    for (int mt = 0; mt < 2; ++mt)
        #pragma unroll
        for (int nt = 0; nt < 4; ++nt)
            #pragma unroll
            for (int j = 0; j < 4; ++j) acc[mt][nt][j] = 0.f;

    mma_layer(sb, SM_AH, SM_AL, SM_BH, SM_BL, acc, wm, wn, lane);

    // ---- epilogue 2: out = selu(acc + b2) -> gmem ----
    {
        const float* b2s = (const float*)(smem + SM_B2S);
        #pragma unroll
        for (int mt = 0; mt < 2; ++mt) {
            int rbase = wm * 32 + mt * 16 + g;
            #pragma unroll
            for (int nt = 0; nt < 4; ++nt) {
                int col = wn * 32 + nt * 8 + 2 * tg;
                float bu = b2s[col], bv = b2s[col + 1];
                if (rbase < rows) {
                    float2 o;
                    o.x = selu_f(acc[mt][nt][0] + bu);
                    o.y = selu_f(acc[mt][nt][1] + bv);
                    *(float2*)(out + (size_t)(r0 + rbase) * (2 * DD) + br * DD + col) = o;
                }
                if (rbase + 8 < rows) {
                    float2 o;
                    o.x = selu_f(acc[mt][nt][2] + bu);
                    o.y = selu_f(acc[mt][nt][3] + bv);
                    *(float2*)(out + (size_t)(r0 + rbase + 8) * (2 * DD) + br * DD + col) = o;
                }
            }
        }
    }
}

// ---------------------------------------------------------------------------
extern "C" void kernel_launch(void* const* d_in, const int* in_sizes, int n_in,
                              void* d_out, int out_size) {
    const float* x_in  = (const float*)d_in[0];
    const int*   erow  = (const int*)d_in[1];
    const int*   ecol  = (const int*)d_in[2];
    const float* evalv = (const float*)d_in[3];
    const float* W1 = (const float*)d_in[4];
    const float* b1 = (const float*)d_in[5];
    const float* W2 = (const float*)d_in[6];
    const float* b2 = (const float*)d_in[7];
    float* out = (float*)d_out;

    int n = in_sizes[0] / DD;      // 100000
    int E = in_sizes[1];           // 1600000

    int n4 = n * DD / 4;
    init_h_kernel<<<(n4 + 255) / 256, 256>>>((const float4*)x_in, n4);

    int warps = (E + EPW - 1) / EPW;
    int sblocks = (warps * 32 + 255) / 256;
    spmm_kernel<<<sblocks, 256>>>((const float4*)x_in, erow, ecol, evalv, E);

    cudaFuncSetAttribute(mlp_mma_kernel, cudaFuncAttributeMaxDynamicSharedMemorySize, SM_TOTAL);
    dim3 grid((n + 127) / 128, 2);
    mlp_mma_kernel<<<grid, MLPT, SM_TOTAL>>>(W1, b1, W2, b2, out, n);
}

// round 17
// speedup vs baseline: 2.0004x; 1.1466x over previous
#include <cuda_runtime.h>
#include <cuda_bf16.h>
#include <cstdint>

#define NN 100000
#define DD 128
#define EPW 64            // edges per warp in spmm

#define SELU_SCALE 1.0507009873554805f
#define SELU_ALPHA 1.6732632423543772f

// Scratch: h_i = spmm(x_in^(i+1)) + x_in^(i+1)   (residual folded into init)
__device__ float g_h0[NN * DD];
__device__ float g_h1[NN * DD];

__device__ __forceinline__ float selu_f(float x) {
    return x > 0.f ? SELU_SCALE * x
                   : (SELU_SCALE * SELU_ALPHA) * (__expf(x) - 1.f);
}

// ---------------------------------------------------------------------------
// Kernel 1: h0 = x_in ; h1 = x_in * x_in   (residual pre-init)
// ---------------------------------------------------------------------------
__global__ void init_h_kernel(const float4* __restrict__ x4, int n4) {
    int i = blockIdx.x * blockDim.x + threadIdx.x;
    if (i >= n4) return;
    float4 v = __ldg(&x4[i]);
    ((float4*)g_h0)[i] = v;
    ((float4*)g_h1)[i] = make_float4(v.x * v.x, v.y * v.y, v.z * v.z, v.w * v.w);
}

// ---------------------------------------------------------------------------
// Kernel 2: fused dual-branch SpMM, 4-edge batched gathers (unchanged)
// ---------------------------------------------------------------------------
__device__ __forceinline__ void flush_row(int r, int lane,
                                          const float4& a0, const float4& a1) {
    float* p0 = g_h0 + (size_t)r * DD + lane * 4;
    float* p1 = g_h1 + (size_t)r * DD + lane * 4;
    atomicAdd(p0 + 0, a0.x); atomicAdd(p0 + 1, a0.y);
    atomicAdd(p0 + 2, a0.z); atomicAdd(p0 + 3, a0.w);
    atomicAdd(p1 + 0, a1.x); atomicAdd(p1 + 1, a1.y);
    atomicAdd(p1 + 2, a1.z); atomicAdd(p1 + 3, a1.w);
}

__global__ void spmm_kernel(const float4* __restrict__ x4,
                            const int*    __restrict__ erow,
                            const int*    __restrict__ ecol,
                            const float*  __restrict__ evalv,
                            int E) {
    int gw   = (blockIdx.x * blockDim.x + threadIdx.x) >> 5;
    int lane = threadIdx.x & 31;
    int e0 = gw * EPW;
    if (e0 >= E) return;
    int e1 = min(e0 + EPW, E);

    float4 a0 = make_float4(0.f, 0.f, 0.f, 0.f);
    float4 a1 = make_float4(0.f, 0.f, 0.f, 0.f);
    int cur = __ldg(erow + e0);

#define ACC1(RR, VV, GG)                                                       \
    do {                                                                       \
        if ((RR) != cur) {                                                     \
            flush_row(cur, lane, a0, a1);                                      \
            a0 = make_float4(0.f, 0.f, 0.f, 0.f);                              \
            a1 = make_float4(0.f, 0.f, 0.f, 0.f);                              \
            cur = (RR);                                                        \
        }                                                                      \
        a0.x = fmaf((VV), (GG).x, a0.x);                                       \
        a0.y = fmaf((VV), (GG).y, a0.y);                                       \
        a0.z = fmaf((VV), (GG).z, a0.z);                                       \
        a0.w = fmaf((VV), (GG).w, a0.w);                                       \
        float vx = (VV) * (GG).x, vy = (VV) * (GG).y;                          \
        float vz = (VV) * (GG).z, vw = (VV) * (GG).w;                          \
        a1.x = fmaf(vx, (GG).x, a1.x);                                         \
        a1.y = fmaf(vy, (GG).y, a1.y);                                         \
        a1.z = fmaf(vz, (GG).z, a1.z);                                         \
        a1.w = fmaf(vw, (GG).w, a1.w);                                         \
    } while (0)

    int e = e0;
    for (; e + 4 <= e1; e += 4) {
        int4   r4 = *(const int4*)(erow + e);
        int4   c4 = *(const int4*)(ecol + e);
        float4 v4 = *(const float4*)(evalv + e);
        float4 g0 = __ldg(&x4[(size_t)c4.x * 32 + lane]);
        float4 g1 = __ldg(&x4[(size_t)c4.y * 32 + lane]);
        float4 g2 = __ldg(&x4[(size_t)c4.z * 32 + lane]);
        float4 g3 = __ldg(&x4[(size_t)c4.w * 32 + lane]);
        ACC1(r4.x, v4.x, g0);
        ACC1(r4.y, v4.y, g1);
        ACC1(r4.z, v4.z, g2);
        ACC1(r4.w, v4.w, g3);
    }
    for (; e < e1; ++e) {
        int   r = __ldg(erow + e);
        int   c = __ldg(ecol + e);
        float v = __ldg(evalv + e);
        float4 g = __ldg(&x4[(size_t)c * 32 + lane]);
        ACC1(r, v, g);
    }
    flush_row(cur, lane, a0, a1);
#undef ACC1
}

// ===========================================================================
// Kernel 3: mma.sync bf16 MLP — 512 threads, 64-row tile, ~105 KB smem,
// __launch_bounds__(512, 2) -> 2 blocks/SM (32 warps/SM) with async phase
// interleaving between co-resident blocks. Deduped split-bf16 mainloop.
// ===========================================================================

#define STRB 272           // padded row stride in bytes (136 bf16)
#define MLPT 512
#define ROWS_T 64

__device__ __forceinline__ uint32_t smem_u32(const void* p) {
    uint32_t a;
    asm("{ .reg .u64 t; cvta.to.shared.u64 t, %1; cvt.u32.u64 %0, t; }"
        : "=r"(a) : "l"(p));
    return a;
}
__device__ __forceinline__ void ldmx4(uint32_t* r, uint32_t addr) {
    asm volatile("ldmatrix.sync.aligned.m8n8.x4.shared.b16 {%0,%1,%2,%3}, [%4];"
                 : "=r"(r[0]), "=r"(r[1]), "=r"(r[2]), "=r"(r[3]) : "r"(addr));
}
__device__ __forceinline__ void ldmx4t(uint32_t* r, uint32_t addr) {
    asm volatile("ldmatrix.sync.aligned.m8n8.x4.trans.shared.b16 {%0,%1,%2,%3}, [%4];"
                 : "=r"(r[0]), "=r"(r[1]), "=r"(r[2]), "=r"(r[3]) : "r"(addr));
}
__device__ __forceinline__ void mma16816(float* c, const uint32_t* a, const uint32_t* b) {
    asm volatile(
        "mma.sync.aligned.m16n8k16.row.col.f32.bf16.bf16.f32 "
        "{%0,%1,%2,%3}, {%4,%5,%6,%7}, {%8,%9}, {%0,%1,%2,%3};"
        : "+f"(c[0]), "+f"(c[1]), "+f"(c[2]), "+f"(c[3])
        : "r"(a[0]), "r"(a[1]), "r"(a[2]), "r"(a[3]), "r"(b[0]), "r"(b[1]));
}

__device__ __forceinline__ void split2(float x0, float x1, uint32_t& hi, uint32_t& lo) {
    __nv_bfloat16 h0 = __float2bfloat16_rn(x0);
    __nv_bfloat16 h1 = __float2bfloat16_rn(x1);
    __nv_bfloat16 l0 = __float2bfloat16_rn(x0 - __bfloat162float(h0));
    __nv_bfloat16 l1 = __float2bfloat16_rn(x1 - __bfloat162float(h1));
    hi = (uint32_t)__bfloat16_as_ushort(h0) | ((uint32_t)__bfloat16_as_ushort(h1) << 16);
    lo = (uint32_t)__bfloat16_as_ushort(l0) | ((uint32_t)__bfloat16_as_ushort(l1) << 16);
}

// SMEM byte offsets: A pair 64 rows, B pair 128 rows, biases. ~105 KB.
#define TSZA (ROWS_T * STRB)       // 17408
#define TSZB (128 * STRB)          // 34816
#define SM_AH 0
#define SM_AL (TSZA)
#define SM_BH (2 * TSZA)
#define SM_BL (2 * TSZA + TSZB)
#define SM_B1S (2 * TSZA + 2 * TSZB)       // float[128]
#define SM_B2S (2 * TSZA + 2 * TSZB + 512)
#define SM_TOTAL (2 * TSZA + 2 * TSZB + 1024)   // 105472 B

// Deduped GEMM layer for a 16x32 warp tile (16 warps: wm 0..3, wn 0..3),
// covering a 64x128 output tile.
__device__ __forceinline__ void mma_layer(uint32_t sb, int aHi, int aLo,
                                          int bHi, int bLo,
                                          float acc[4][4],
                                          int wm, int wn, int lane) {
    int arow = wm * 16 + (lane & 15);
    int akh  = 8 * (lane >> 4);
    int bkr  = (lane & 7) + 8 * ((lane >> 3) & 1);
    int bnc  = wn * 32 + 8 * (lane >> 4);

    #pragma unroll
    for (int kc = 0; kc < 8; ++kc) {
        int k = kc * 16;
        uint32_t ah[4], al[4];
        ldmx4(ah, sb + aHi + arow * STRB + (k + akh) * 2);
        ldmx4(al, sb + aLo + arow * STRB + (k + akh) * 2);
        #pragma unroll
        for (int np = 0; np < 2; ++np) {
            uint32_t bh[4], bl[4];
            ldmx4t(bh, sb + bHi + (k + bkr) * STRB + (bnc + np * 16) * 2);
            ldmx4t(bl, sb + bLo + (k + bkr) * STRB + (bnc + np * 16) * 2);
            #pragma unroll
            for (int hh = 0; hh < 2; ++hh) {
                float* c = acc[np * 2 + hh];
                mma16816(c, ah, bh + 2 * hh);
                mma16816(c, ah, bl + 2 * hh);
                mma16816(c, al, bh + 2 * hh);
            }
        }
    }
}

__global__ void __launch_bounds__(MLPT, 2)
mlp_mma_kernel(const float* __restrict__ W1, const float* __restrict__ b1,
               const float* __restrict__ W2, const float* __restrict__ b2,
               float* __restrict__ out, int n) {
    extern __shared__ char smem[];
    uint32_t sb = smem_u32(smem);
    int tid = threadIdx.x, wid = tid >> 5, lane = tid & 31;
    int wm = wid & 3, wn = wid >> 2;            // 4x4 warp grid, 16x32 tiles
    int g = lane >> 2, tg = lane & 3;           // mma C-frag coords
    int br = blockIdx.y;
    int r0 = blockIdx.x * ROWS_T;
    int rows = min(ROWS_T, n - r0);
    const float* h  = (br ? g_h1 : g_h0) + (size_t)r0 * DD;
    const float* w1 = W1 + (size_t)br * DD * DD;
    const float* w2 = W2 + (size_t)br * DD * DD;

    if (tid < 128) {
        ((float*)(smem + SM_B1S))[tid] = __ldg(b1 + (size_t)br * DD + tid);
        ((float*)(smem + SM_B2S))[tid] = __ldg(b2 + (size_t)br * DD + tid);
    }

    // ---- A tile: 64 h rows -> split bf16, [row][k], stride 136 ----
    for (int i = tid; i < ROWS_T * 32; i += MLPT) {
        int r = i >> 5, k = (i & 31) * 4;
        float4 v = (r < rows) ? __ldg((const float4*)(h + (size_t)r * DD + k))
                              : make_float4(0.f, 0.f, 0.f, 0.f);
        uint32_t hi0, lo0, hi1, lo1;
        split2(v.x, v.y, hi0, lo0);
        split2(v.z, v.w, hi1, lo1);
        char* pAH = smem + SM_AH + r * STRB + k * 2;
        char* pAL = smem + SM_AL + r * STRB + k * 2;
        *(uint32_t*)(pAH)     = hi0; *(uint32_t*)(pAH + 4) = hi1;
        *(uint32_t*)(pAL)     = lo0; *(uint32_t*)(pAL + 4) = lo1;
    }
    // ---- B tile: W1 as-is [k][n] -> split bf16, stride 136 ----
    for (int i = tid; i < 128 * 32; i += MLPT) {
        int k = i >> 5, nb = (i & 31) * 4;
        float4 v = __ldg((const float4*)(w1 + (size_t)k * DD + nb));
        uint32_t hi0, lo0, hi1, lo1;
        split2(v.x, v.y, hi0, lo0);
        split2(v.z, v.w, hi1, lo1);
        char* pBH = smem + SM_BH + k * STRB + nb * 2;
        char* pBL = smem + SM_BL + k * STRB + nb * 2;
        *(uint32_t*)(pBH)     = hi0; *(uint32_t*)(pBH + 4) = hi1;
        *(uint32_t*)(pBL)     = lo0; *(uint32_t*)(pBL + 4) = lo1;
    }
    __syncthreads();

    // ---- layer 1 ----
    float acc[4][4];
    #pragma unroll
    for (int nt = 0; nt < 4; ++nt)
        #pragma unroll
        for (int j = 0; j < 4; ++j) acc[nt][j] = 0.f;

    mma_layer(sb, SM_AH, SM_AL, SM_BH, SM_BL, acc, wm, wn, lane);
    __syncthreads();   // all reads of A/B done before T overwrites A

    // ---- epilogue 1: T = selu(acc + b1) -> re-split into A buffers ----
    {
        const float* b1s = (const float*)(smem + SM_B1S);
        int rbase = wm * 16 + g;
        #pragma unroll
        for (int nt = 0; nt < 4; ++nt) {
            int col = wn * 32 + nt * 8 + 2 * tg;
            float bu = b1s[col], bv = b1s[col + 1];
            uint32_t hi, lo;
            split2(selu_f(acc[nt][0] + bu), selu_f(acc[nt][1] + bv), hi, lo);
            *(uint32_t*)(smem + SM_AH + rbase * STRB + col * 2) = hi;
            *(uint32_t*)(smem + SM_AL + rbase * STRB + col * 2) = lo;
            split2(selu_f(acc[nt][2] + bu), selu_f(acc[nt][3] + bv), hi, lo);
            *(uint32_t*)(smem + SM_AH + (rbase + 8) * STRB + col * 2) = hi;
            *(uint32_t*)(smem + SM_AL + (rbase + 8) * STRB + col * 2) = lo;
        }
    }
    // ---- overwrite B with W2 (same phase) ----
    for (int i = tid; i < 128 * 32; i += MLPT) {
        int k = i >> 5, nb = (i & 31) * 4;
        float4 v = __ldg((const float4*)(w2 + (size_t)k * DD + nb));
        uint32_t hi0, lo0, hi1, lo1;
        split2(v.x, v.y, hi0, lo0);
        split2(v.z, v.w, hi1, lo1);
        char* pBH = smem + SM_BH + k * STRB + nb * 2;
        char* pBL = smem + SM_BL + k * STRB + nb * 2;
        *(uint32_t*)(pBH)     = hi0; *(uint32_t*)(pBH + 4) = hi1;
        *(uint32_t*)(pBL)     = lo0; *(uint32_t*)(pBL + 4) = lo1;
    }
    __syncthreads();

    // ---- layer 2 ----
    #pragma unroll
    for (int nt = 0; nt < 4; ++nt)
        #pragma unroll
        for (int j = 0; j < 4; ++j) acc[nt][j] = 0.f;

    mma_layer(sb, SM_AH, SM_AL, SM_BH, SM_BL, acc, wm, wn, lane);

    // ---- epilogue 2: out = selu(acc + b2) -> gmem ----
    {
        const float* b2s = (const float*)(smem + SM_B2S);
        int rbase = wm * 16 + g;
        #pragma unroll
        for (int nt = 0; nt < 4; ++nt) {
            int col = wn * 32 + nt * 8 + 2 * tg;
            float bu = b2s[col], bv = b2s[col + 1];
            if (rbase < rows) {
                float2 o;
                o.x = selu_f(acc[nt][0] + bu);
                o.y = selu_f(acc[nt][1] + bv);
                *(float2*)(out + (size_t)(r0 + rbase) * (2 * DD) + br * DD + col) = o;
            }
            if (rbase + 8 < rows) {
                float2 o;
                o.x = selu_f(acc[nt][2] + bu);
                o.y = selu_f(acc[nt][3] + bv);
                *(float2*)(out + (size_t)(r0 + rbase + 8) * (2 * DD) + br * DD + col) = o;
            }
        }
    }
}

// ---------------------------------------------------------------------------
extern "C" void kernel_launch(void* const* d_in, const int* in_sizes, int n_in,
                              void* d_out, int out_size) {
    const float* x_in  = (const float*)d_in[0];
    const int*   erow  = (const int*)d_in[1];
    const int*   ecol  = (const int*)d_in[2];
    const float* evalv = (const float*)d_in[3];
    const float* W1 = (const float*)d_in[4];
    const float* b1 = (const float*)d_in[5];
    const float* W2 = (const float*)d_in[6];
    const float* b2 = (const float*)d_in[7];
    float* out = (float*)d_out;

    int n = in_sizes[0] / DD;      // 100000
    int E = in_sizes[1];           // 1600000

    int n4 = n * DD / 4;
    init_h_kernel<<<(n4 + 255) / 256, 256>>>((const float4*)x_in, n4);

    int warps = (E + EPW - 1) / EPW;
    int sblocks = (warps * 32 + 255) / 256;
    spmm_kernel<<<sblocks, 256>>>((const float4*)x_in, erow, ecol, evalv, E);

    cudaFuncSetAttribute(mlp_mma_kernel, cudaFuncAttributeMaxDynamicSharedMemorySize, SM_TOTAL);
    dim3 grid((n + ROWS_T - 1) / ROWS_T, 2);
    mlp_mma_kernel<<<grid, MLPT, SM_TOTAL>>>(W1, b1, W2, b2, out, n);
}